// round 14
// baseline (speedup 1.0000x reference)
#include <cuda_runtime.h>
#include <cuda_fp16.h>
#include <cstdint>

#define N_ROWS 8192
#define D      256
#define K      8192
#define DEPTH  4
#define CB_STRIDE ((K + 1) * D)
#define LOSS_SCALE (0.25f / (4.0f * 2097152.0f))
#define MARGIN 8e-3f
#define FLT_BIG 3.402823466e38f

#define BM 256
#define BN 128
#define ATILE 32768                  // 256 rows x 128B per k-chunk
#define BTILE 16384                  // 128 rows x 128B per k-chunk
#define STG   (ATILE + BTILE)        // 49152
#define NSTG  3
#define SMEMT (NSTG * STG)           // 147456 -> 1 CTA/SM (reg-bound anyway)

// ---------------- persistent scratch ----------------
__device__ __align__(256) float  g_res[N_ROWS * D];
__device__ __align__(256) float  g_agg[N_ROWS * D];
__device__ __align__(256) __half g_res_h[N_ROWS * D];
__device__ __align__(256) __half g_cb_h[DEPTH * K * D];
__device__ __align__(16)  float  g_cc[DEPTH * K];
__device__ __align__(16)  unsigned long long g_top[N_ROWS * 128];  // 64 tiles x top-2

// ---------------- helpers ----------------
__device__ __forceinline__ uint32_t smem_u32(const void* p) {
    uint32_t a;
    asm("{ .reg .u64 t; cvta.to.shared.u64 t, %1; cvt.u32.u64 %0, t; }" : "=r"(a) : "l"(p));
    return a;
}
__device__ __forceinline__ uint32_t swz(uint32_t x) { return x ^ ((x >> 3) & 0x70u); }
__device__ __forceinline__ uint32_t h2_as_u32(__half2 h) {
    return *reinterpret_cast<uint32_t*>(&h);
}
__device__ __forceinline__ unsigned int f2ord(float f) {
    unsigned int u = __float_as_uint(f);
    return (u & 0x80000000u) ? ~u : (u | 0x80000000u);
}
__device__ __forceinline__ float ord2f(unsigned int o) {
    unsigned int u = (o & 0x80000000u) ? (o & 0x7FFFFFFFu) : ~o;
    return __uint_as_float(u);
}
__device__ __forceinline__ void merge2(unsigned long long& b1, unsigned long long& b2,
                                       unsigned long long o1, unsigned long long o2) {
    if (o1 < b1) { b2 = (b1 < o2) ? b1 : o2; b1 = o1; }
    else if (o1 < b2) { b2 = o1; }
}
__device__ __forceinline__ void push2(unsigned long long& b1, unsigned long long& b2,
                                      unsigned long long k) {
    if (k < b1) { b2 = b1; b1 = k; }
    else if (k < b2) { b2 = k; }
}

__device__ __forceinline__ void cpa16(uint32_t dst, const void* src) {
    asm volatile("cp.async.cg.shared.global [%0], [%1], 16;" :: "r"(dst), "l"(src));
}
#define CP_COMMIT() asm volatile("cp.async.commit_group;" ::: "memory")
#define CP_WAIT(n)  asm volatile("cp.async.wait_group %0;" :: "n"(n) : "memory")

#define LDSM4(r0, r1, r2, r3, a) \
    asm volatile("ldmatrix.sync.aligned.m8n8.x4.shared.b16 {%0,%1,%2,%3}, [%4];" \
                 : "=r"(r0), "=r"(r1), "=r"(r2), "=r"(r3) : "r"(a))

#define MMA16816(c, a, b0, b1) \
    asm volatile("mma.sync.aligned.m16n8k16.row.col.f32.f16.f16.f32 " \
                 "{%0,%1,%2,%3},{%4,%5,%6,%7},{%8,%9},{%0,%1,%2,%3};" \
                 : "+f"((c)[0]), "+f"((c)[1]), "+f"((c)[2]), "+f"((c)[3]) \
                 : "r"((a)[0]), "r"((a)[1]), "r"((a)[2]), "r"((a)[3]), "r"(b0), "r"(b1))

// reduce two values across a 256-thread block; result in thread 0
__device__ __forceinline__ void blockReduce2_256(float& a, float& b) {
    __shared__ float sa[8], sb2[8];
    int lane = threadIdx.x & 31, w = threadIdx.x >> 5;
#pragma unroll
    for (int o = 16; o > 0; o >>= 1) {
        a += __shfl_down_sync(0xffffffffu, a, o);
        b += __shfl_down_sync(0xffffffffu, b, o);
    }
    if (lane == 0) { sa[w] = a; sb2[w] = b; }
    __syncthreads();
    if (w == 0) {
        a = (lane < 8) ? sa[lane] : 0.f;
        b = (lane < 8) ? sb2[lane] : 0.f;
#pragma unroll
        for (int o = 4; o > 0; o >>= 1) {
            a += __shfl_down_sync(0xffu, a, o);
            b += __shfl_down_sync(0xffu, b, o);
        }
    }
}

// ---------------- setup ----------------
__global__ void k_init(const float* __restrict__ x) {
    int i = blockIdx.x * blockDim.x + threadIdx.x;
    if (i < N_ROWS * D) {
        float v = x[i];
        g_res[i] = v; g_agg[i] = 0.f;
        g_res_h[i] = __float2half_rn(v);
    }
}

__global__ void k_cb(const float* __restrict__ cbs) {
    int rid = blockIdx.x;                     // 0 .. DEPTH*K-1
    int dd = rid / K, r = rid % K;
    float v = cbs[(size_t)dd * CB_STRIDE + (size_t)r * D + threadIdx.x];
    g_cb_h[(size_t)rid * D + threadIdx.x] = __float2half_rn(v);
    float a = v * v, b = 0.f;
    blockReduce2_256(a, b);
    if (threadIdx.x == 0) g_cc[rid] = a;
}

__global__ void k_zero(float* __restrict__ loss) {
    if (threadIdx.x == 0) *loss = 0.f;
}

// ---------------- HMMA GEMM: 512 threads, CTA 256x128, 4 K-iterations ----------
// grid = (32, 64), block = 512 (16 warps: wm=wid&3 row 64-groups, wn=wid>>2
// col 32-groups). Warp tile 64x32 (acc 64 regs). 3-stage A+B pipeline.
__global__ void __launch_bounds__(512, 1) k_gemm(int dep) {
    extern __shared__ char smem[];
    const uint32_t sb = smem_u32(smem);
    const int tid = threadIdx.x, lane = tid & 31, wid = tid >> 5;
    const int wm = wid & 3, wn = wid >> 2;
    const int rowBase = blockIdx.x * BM, candBase = blockIdx.y * BN;

    const char* Ag = (const char*)(g_res_h + (size_t)rowBase * D);
    const char* Bg = (const char*)(g_cb_h + ((size_t)dep * K + (size_t)candBase) * D);

    const int r0 = tid >> 3, j0 = tid & 7;           // r0: 0..63
    uint32_t sdA[4], sdB[2];
#pragma unroll
    for (int i = 0; i < 4; i++) sdA[i] = swz((uint32_t)(r0 + i * 64) * 128u + j0 * 16u);
#pragma unroll
    for (int i = 0; i < 2; i++) sdB[i] = swz((uint32_t)(r0 + i * 64) * 128u + j0 * 16u);
    const uint32_t gOff = (uint32_t)r0 * 512u + (uint32_t)j0 * 16u;

    float acc[4][4][4];
#pragma unroll
    for (int a = 0; a < 4; a++)
#pragma unroll
        for (int b = 0; b < 4; b++)
#pragma unroll
            for (int q = 0; q < 4; q++) acc[a][b][q] = 0.f;

    const uint32_t aLin = (uint32_t)((wm * 64 + (lane & 15)) * 128 + (lane >> 4) * 16);
    const uint32_t bLin = (uint32_t)((wn * 32 + (lane & 7) + ((lane >> 4) << 3)) * 128 +
                                     ((lane >> 3) & 1) * 16);

    // prologue: chunk0 -> stage0, chunk1 -> stage1 (two groups)
#pragma unroll
    for (int pc = 0; pc < 2; pc++) {
        const uint32_t stg = (uint32_t)pc * STG;
        const uint32_t ko = (uint32_t)pc * 128u;
#pragma unroll
        for (int i = 0; i < 4; i++)
            cpa16(sb + stg + sdA[i], Ag + gOff + i * 64u * 512u + ko);
#pragma unroll
        for (int i = 0; i < 2; i++)
            cpa16(sb + stg + ATILE + sdB[i], Bg + gOff + i * 64u * 512u + ko);
        CP_COMMIT();
    }

#pragma unroll
    for (int kc = 0; kc < 4; kc++) {
        if (kc < 3) { CP_WAIT(1); } else { CP_WAIT(0); }
        __syncthreads();

        if (kc + 2 < 4) {
            const uint32_t stg = (uint32_t)((kc + 2) % NSTG) * STG;
            const uint32_t ko = (uint32_t)(kc + 2) * 128u;
#pragma unroll
            for (int i = 0; i < 4; i++)
                cpa16(sb + stg + sdA[i], Ag + gOff + i * 64u * 512u + ko);
#pragma unroll
            for (int i = 0; i < 2; i++)
                cpa16(sb + stg + ATILE + sdB[i], Bg + gOff + i * 64u * 512u + ko);
            CP_COMMIT();
        }

        const uint32_t aT = sb + (uint32_t)(kc % NSTG) * STG;
        const uint32_t bT = aT + ATILE;
#pragma unroll
        for (int ks = 0; ks < 4; ks++) {
            uint32_t Af[4][4], Bf[2][4];
#pragma unroll
            for (int ma = 0; ma < 4; ma++)
                LDSM4(Af[ma][0], Af[ma][1], Af[ma][2], Af[ma][3],
                      aT + swz(aLin + ma * 2048 + ks * 32));
#pragma unroll
            for (int nb = 0; nb < 2; nb++)
                LDSM4(Bf[nb][0], Bf[nb][1], Bf[nb][2], Bf[nb][3],
                      bT + swz(bLin + nb * 2048 + ks * 32));
#pragma unroll
            for (int ma = 0; ma < 4; ma++)
#pragma unroll
                for (int nb = 0; nb < 2; nb++) {
                    MMA16816(acc[ma][2 * nb + 0], Af[ma], Bf[nb][0], Bf[nb][1]);
                    MMA16816(acc[ma][2 * nb + 1], Af[ma], Bf[nb][2], Bf[nb][3]);
                }
        }
    }

    // ---- epilogue: per-row top-2 over this CTA's 128 cols ----
    __syncthreads();                    // all smem reads done; alias sTop
    unsigned long long* sTop = (unsigned long long*)smem;   // [256 rows][4 wn][2]
    const float* cc = g_cc + (size_t)dep * K;
    const int colBase = candBase + wn * 32 + (lane & 3) * 2;

    float2 ccv[4];
#pragma unroll
    for (int g = 0; g < 4; g++) ccv[g] = *(const float2*)&cc[colBase + g * 8];

#pragma unroll
    for (int ma = 0; ma < 4; ma++) {
#pragma unroll
        for (int rb = 0; rb < 2; rb++) {
            float d1 = FLT_BIG, d2 = FLT_BIG;
            int i1 = 0, i2 = 0;
#pragma unroll
            for (int g = 0; g < 4; g++) {
                const int col = colBase + g * 8;
                float k0 = fmaf(-2.f, acc[ma][g][rb * 2 + 0], ccv[g].x);
                float k1 = fmaf(-2.f, acc[ma][g][rb * 2 + 1], ccv[g].y);
                if (k0 < d2) {
                    if (k0 < d1) { d2 = d1; i2 = i1; d1 = k0; i1 = col; }
                    else { d2 = k0; i2 = col; }
                }
                if (k1 < d2) {
                    if (k1 < d1) { d2 = d1; i2 = i1; d1 = k1; i1 = col + 1; }
                    else { d2 = k1; i2 = col + 1; }
                }
            }
            unsigned long long b1 =
                ((unsigned long long)f2ord(d1) << 32) | (unsigned int)i1;
            unsigned long long b2 =
                ((unsigned long long)f2ord(d2) << 32) | (unsigned int)i2;
#pragma unroll
            for (int off = 1; off <= 2; off <<= 1) {
                unsigned long long o1 = __shfl_xor_sync(0xffffffffu, b1, off);
                unsigned long long o2 = __shfl_xor_sync(0xffffffffu, b2, off);
                merge2(b1, b2, o1, o2);
            }
            if ((lane & 3) == 0) {
                int rl = wm * 64 + ma * 16 + rb * 8 + (lane >> 2);
                sTop[(rl * 4 + wn) * 2 + 0] = b1;
                sTop[(rl * 4 + wn) * 2 + 1] = b2;
            }
        }
    }
    __syncthreads();
    if (tid < 256) {
        unsigned long long p1 = sTop[tid * 8 + 0];
        unsigned long long p2 = sTop[tid * 8 + 1];
#pragma unroll
        for (int j = 1; j < 4; j++)
            merge2(p1, p2, sTop[tid * 8 + j * 2], sTop[tid * 8 + j * 2 + 1]);
        size_t go = (size_t)(rowBase + tid) * 128 + blockIdx.y * 2;
        g_top[go + 0] = p1;
        g_top[go + 1] = p2;
    }
}

// ---------------- fused select + rescore + update: warp per row ----------------
// grid = N_ROWS/8 = 1024, block = 256 (8 warps)
__global__ void __launch_bounds__(256) k_finish(
        const float* __restrict__ x, const float* __restrict__ cb,
        float* __restrict__ out, float* __restrict__ codes,
        float* __restrict__ loss, int dep) {
    const int w = threadIdx.x >> 5, lane = threadIdx.x & 31;
    const int row = blockIdx.x * 8 + w;
    __shared__ unsigned long long se[8][128];
    __shared__ int sql[8][128];
    __shared__ float wloss[8];

    const unsigned long long* gt = g_top + (size_t)row * 128;
    unsigned long long b1 = ~0ull, b2 = ~0ull;
#pragma unroll
    for (int i = 0; i < 4; i++) {
        unsigned long long e = gt[lane + i * 32];
        se[w][lane + i * 32] = e;
        push2(b1, b2, e);
    }
#pragma unroll
    for (int off = 16; off > 0; off >>= 1) {
        unsigned long long o1 = __shfl_xor_sync(0xffffffffu, b1, off);
        unsigned long long o2 = __shfl_xor_sync(0xffffffffu, b2, off);
        merge2(b1, b2, o1, o2);
    }
    float d1 = ord2f((unsigned int)(b1 >> 32));
    float d2 = ord2f((unsigned int)(b2 >> 32));
    int idx = (int)(b1 & 0xFFFFFFFFu);

    const float4* rr = (const float4*)(g_res + (size_t)row * D);
    float4 r0 = rr[lane * 2], r1 = rr[lane * 2 + 1];

    if (d2 - d1 < MARGIN) {
        const float thr = d1 + MARGIN;
        int nq = 0;
        __syncwarp();
#pragma unroll
        for (int i = 0; i < 4; i++) {
            unsigned long long e = se[w][lane + i * 32];
            bool qf = ord2f((unsigned int)(e >> 32)) <= thr;
            unsigned m = __ballot_sync(0xffffffffu, qf);
            if (qf) {
                int pos = nq + __popc(m & ((1u << lane) - 1u));
                sql[w][pos] = (int)(e & 0xFFFFFFFFu);
            }
            nq += __popc(m);
        }
        __syncwarp();
        unsigned long long best = ~0ull;
        const float* ccd = g_cc + (size_t)dep * K;
        for (int q = 0; q < nq; q++) {
            int cand = sql[w][q];
            const float4* cr = (const float4*)(cb + (size_t)cand * D);
            float4 c0 = cr[lane * 2], c1 = cr[lane * 2 + 1];
            float p = r0.x * c0.x + r0.y * c0.y + r0.z * c0.z + r0.w * c0.w
                    + r1.x * c1.x + r1.y * c1.y + r1.z * c1.z + r1.w * c1.w;
#pragma unroll
            for (int o = 16; o > 0; o >>= 1) p += __shfl_xor_sync(0xffffffffu, p, o);
            float dist = ccd[cand] - 2.f * p;
            unsigned long long key =
                ((unsigned long long)f2ord(dist) << 32) | (unsigned int)cand;
            if (key < best) best = key;
        }
        idx = (int)(best & 0xFFFFFFFFu);
    }

    const size_t o4 = (size_t)row * (D / 4) + lane * 2;
    const float4* cbv = (const float4*)(cb + (size_t)idx * D);
    float4 q0 = cbv[lane * 2], q1 = cbv[lane * 2 + 1];
    float4 a0 = ((const float4*)g_agg)[o4], a1 = ((const float4*)g_agg)[o4 + 1];
    a0.x += q0.x; a0.y += q0.y; a0.z += q0.z; a0.w += q0.w;
    a1.x += q1.x; a1.y += q1.y; a1.z += q1.z; a1.w += q1.w;
    float4 x0 = ((const float4*)x)[o4], x1 = ((const float4*)x)[o4 + 1];

    if (dep < DEPTH - 1) {
        float4 n0, n1;
        n0.x = r0.x - q0.x; n0.y = r0.y - q0.y; n0.z = r0.z - q0.z; n0.w = r0.w - q0.w;
        n1.x = r1.x - q1.x; n1.y = r1.y - q1.y; n1.z = r1.z - q1.z; n1.w = r1.w - q1.w;
        ((float4*)g_res)[o4] = n0;
        ((float4*)g_res)[o4 + 1] = n1;
        uint4 hh;
        hh.x = h2_as_u32(__float22half2_rn(make_float2(n0.x, n0.y)));
        hh.y = h2_as_u32(__float22half2_rn(make_float2(n0.z, n0.w)));
        hh.z = h2_as_u32(__float22half2_rn(make_float2(n1.x, n1.y)));
        hh.w = h2_as_u32(__float22half2_rn(make_float2(n1.z, n1.w)));
        *(uint4*)(g_res_h + (size_t)row * D + lane * 8) = hh;
        ((float4*)g_agg)[o4] = a0;
        ((float4*)g_agg)[o4 + 1] = a1;
    } else {
        float4 ov0, ov1;
        ov0.x = x0.x + (a0.x - x0.x); ov0.y = x0.y + (a0.y - x0.y);
        ov0.z = x0.z + (a0.z - x0.z); ov0.w = x0.w + (a0.w - x0.w);
        ov1.x = x1.x + (a1.x - x1.x); ov1.y = x1.y + (a1.y - x1.y);
        ov1.z = x1.z + (a1.z - x1.z); ov1.w = x1.w + (a1.w - x1.w);
        ((float4*)out)[o4] = ov0;
        ((float4*)out)[o4 + 1] = ov1;
    }

    float d0x = x0.x - a0.x, d0y = x0.y - a0.y, d0z = x0.z - a0.z, d0w = x0.w - a0.w;
    float d1x = x1.x - a1.x, d1y = x1.y - a1.y, d1z = x1.z - a1.z, d1w = x1.w - a1.w;
    float s2 = d0x * d0x + d0y * d0y + d0z * d0z + d0w * d0w
             + d1x * d1x + d1y * d1y + d1z * d1z + d1w * d1w;
#pragma unroll
    for (int o = 16; o > 0; o >>= 1) s2 += __shfl_down_sync(0xffffffffu, s2, o);
    if (lane == 0) {
        wloss[w] = s2;
        codes[(size_t)row * DEPTH + dep] = (float)idx;
    }
    __syncthreads();
    if (threadIdx.x == 0) {
        float t = 0.f;
#pragma unroll
        for (int i = 0; i < 8; i++) t += wloss[i];
        atomicAdd(loss, t * LOSS_SCALE);
    }
}

extern "C" void kernel_launch(void* const* d_in, const int* in_sizes, int n_in,
                              void* d_out, int out_size) {
    const float* x = (const float*)d_in[0];
    const float* cbs = (const float*)d_in[1];
    float* out = (float*)d_out;
    float* loss = out + (size_t)N_ROWS * D;
    float* codes = loss + 1;

    cudaFuncSetAttribute(k_gemm, cudaFuncAttributeMaxDynamicSharedMemorySize, SMEMT);

    k_init<<<(N_ROWS * D + 255) / 256, 256>>>(x);         // launch 0
    k_cb<<<DEPTH * K, 256>>>(cbs);                        // launch 1
    k_zero<<<1, 32>>>(loss);                              // launch 2

    for (int d = 0; d < DEPTH; d++) {
        const float* cb = cbs + (size_t)d * CB_STRIDE;
        dim3 grid(N_ROWS / BM, K / BN);
        k_gemm<<<grid, 512, SMEMT>>>(d);                  // launches 3,5,7,9
        k_finish<<<N_ROWS / 8, 256>>>(x, cb, out, codes, loss, d);
    }
}

// round 15
// speedup vs baseline: 1.2781x; 1.2781x over previous
#include <cuda_runtime.h>
#include <cuda_fp16.h>
#include <cstdint>

#define N_ROWS 8192
#define D      256
#define K      8192
#define DEPTH  4
#define CB_STRIDE ((K + 1) * D)
#define LOSS_SCALE (0.25f / (4.0f * 2097152.0f))
#define MARGIN 8e-3f
#define FLT_BIG 3.402823466e38f

#define BM 128
#define TILE16 16384                 // 128 rows x 128B, pad-free (XOR swizzle)
#define SM_B  (4 * TILE16)           // A resident: 4 chunk tiles = 65536
#define NBSTG 3
#define SMEMT (SM_B + NBSTG * TILE16)   // 114688 -> 2 CTAs/SM

// ---------------- persistent scratch ----------------
__device__ __align__(256) float  g_res[N_ROWS * D];
__device__ __align__(256) float  g_agg[N_ROWS * D];
__device__ __align__(256) __half g_res_h[N_ROWS * D];
__device__ __align__(256) __half g_cb_h[DEPTH * K * D];
__device__ __align__(16)  float  g_cc[DEPTH * K];
__device__ __align__(16)  unsigned long long g_top[N_ROWS * 64];   // 32 tiles x top-2

// ---------------- helpers ----------------
__device__ __forceinline__ uint32_t smem_u32(const void* p) {
    uint32_t a;
    asm("{ .reg .u64 t; cvta.to.shared.u64 t, %1; cvt.u32.u64 %0, t; }" : "=r"(a) : "l"(p));
    return a;
}
__device__ __forceinline__ uint32_t swz(uint32_t x) { return x ^ ((x >> 3) & 0x70u); }
__device__ __forceinline__ uint32_t h2_as_u32(__half2 h) {
    return *reinterpret_cast<uint32_t*>(&h);
}
__device__ __forceinline__ unsigned int f2ord(float f) {
    unsigned int u = __float_as_uint(f);
    return (u & 0x80000000u) ? ~u : (u | 0x80000000u);
}
__device__ __forceinline__ float ord2f(unsigned int o) {
    unsigned int u = (o & 0x80000000u) ? (o & 0x7FFFFFFFu) : ~o;
    return __uint_as_float(u);
}
__device__ __forceinline__ void merge2(unsigned long long& b1, unsigned long long& b2,
                                       unsigned long long o1, unsigned long long o2) {
    if (o1 < b1) { b2 = (b1 < o2) ? b1 : o2; b1 = o1; }
    else if (o1 < b2) { b2 = o1; }
}
__device__ __forceinline__ void push2(unsigned long long& b1, unsigned long long& b2,
                                      unsigned long long k) {
    if (k < b1) { b2 = b1; b1 = k; }
    else if (k < b2) { b2 = k; }
}

__device__ __forceinline__ void cpa16(uint32_t dst, const void* src) {
    asm volatile("cp.async.cg.shared.global [%0], [%1], 16;" :: "r"(dst), "l"(src));
}
#define CP_COMMIT() asm volatile("cp.async.commit_group;" ::: "memory")
#define CP_WAIT(n)  asm volatile("cp.async.wait_group %0;" :: "n"(n) : "memory")

#define LDSM4(r0, r1, r2, r3, a) \
    asm volatile("ldmatrix.sync.aligned.m8n8.x4.shared.b16 {%0,%1,%2,%3}, [%4];" \
                 : "=r"(r0), "=r"(r1), "=r"(r2), "=r"(r3) : "r"(a))

#define MMA16816(c, a, b0, b1) \
    asm volatile("mma.sync.aligned.m16n8k16.row.col.f32.f16.f16.f32 " \
                 "{%0,%1,%2,%3},{%4,%5,%6,%7},{%8,%9},{%0,%1,%2,%3};" \
                 : "+f"((c)[0]), "+f"((c)[1]), "+f"((c)[2]), "+f"((c)[3]) \
                 : "r"((a)[0]), "r"((a)[1]), "r"((a)[2]), "r"((a)[3]), "r"(b0), "r"(b1))

// reduce two values across a 256-thread block; result in thread 0
__device__ __forceinline__ void blockReduce2_256(float& a, float& b) {
    __shared__ float sa[8], sb2[8];
    int lane = threadIdx.x & 31, w = threadIdx.x >> 5;
#pragma unroll
    for (int o = 16; o > 0; o >>= 1) {
        a += __shfl_down_sync(0xffffffffu, a, o);
        b += __shfl_down_sync(0xffffffffu, b, o);
    }
    if (lane == 0) { sa[w] = a; sb2[w] = b; }
    __syncthreads();
    if (w == 0) {
        a = (lane < 8) ? sa[lane] : 0.f;
        b = (lane < 8) ? sb2[lane] : 0.f;
#pragma unroll
        for (int o = 4; o > 0; o >>= 1) {
            a += __shfl_down_sync(0xffu, a, o);
            b += __shfl_down_sync(0xffu, b, o);
        }
    }
}

// ---------------- setup ----------------
__global__ void k_init(const float* __restrict__ x, float* __restrict__ loss) {
    int i = blockIdx.x * blockDim.x + threadIdx.x;
    if (i < N_ROWS * D) {
        float v = x[i];
        g_res[i] = v; g_agg[i] = 0.f;
        g_res_h[i] = __float2half_rn(v);
    }
    if (i == 0) *loss = 0.f;
}

__global__ void k_cb(const float* __restrict__ cbs) {
    int rid = blockIdx.x;                     // 0 .. DEPTH*K-1
    int dd = rid / K, r = rid % K;
    float v = cbs[(size_t)dd * CB_STRIDE + (size_t)r * D + threadIdx.x];
    g_cb_h[(size_t)rid * D + threadIdx.x] = __float2half_rn(v);
    float a = v * v, b = 0.f;
    blockReduce2_256(a, b);
    if (threadIdx.x == 0) g_cc[rid] = a;
}

// consume one 128-col sub-tile's accumulators into running float top-2
__device__ __forceinline__ void consume_acc(
        float acc[2][8][4], const float* __restrict__ cc, int colBase,
        float d1[4], float d2[4], int i1[4], int i2[4]) {
#pragma unroll
    for (int mb = 0; mb < 2; mb++) {
#pragma unroll
        for (int rb = 0; rb < 2; rb++) {
            const int s = mb * 2 + rb;
#pragma unroll
            for (int nf = 0; nf < 8; nf++) {
                int col = colBase + nf * 8;
                float2 c2 = *(const float2*)&cc[col];
                float k0 = fmaf(-2.f, acc[mb][nf][rb * 2 + 0], c2.x);
                float k1 = fmaf(-2.f, acc[mb][nf][rb * 2 + 1], c2.y);
                if (k0 < d2[s]) {
                    if (k0 < d1[s]) { d2[s] = d1[s]; i2[s] = i1[s]; d1[s] = k0; i1[s] = col; }
                    else { d2[s] = k0; i2[s] = col; }
                }
                if (k1 < d2[s]) {
                    if (k1 < d1[s]) { d2[s] = d1[s]; i2[s] = i1[s]; d1[s] = k1; i1[s] = col + 1; }
                    else { d2[s] = k1; i2[s] = col + 1; }
                }
                acc[mb][nf][rb * 2 + 0] = 0.f;
                acc[mb][nf][rb * 2 + 1] = 0.f;
            }
        }
    }
}

// ---------------- HMMA GEMM + per-CTA top-2 (R10 configuration) ----------------
// grid = (64, 32), block = 256 (8 warps: 4 row x 2 col)
// A (128x256) resident (XOR-swizzled, pad-free); B streamed through 3 stages,
// prefetch distance 2 (CP_WAIT(1)).
__global__ void __launch_bounds__(256, 2) k_gemm(int dep) {
    extern __shared__ char smem[];
    const uint32_t sb = smem_u32(smem);
    const int tid = threadIdx.x, lane = tid & 31, wid = tid >> 5;
    const int wm = wid & 3, wn = wid >> 2;
    const int rowBase = blockIdx.x * BM, candBase = blockIdx.y * 256;

    const char* Ag = (const char*)(g_res_h + (size_t)rowBase * D);
    const char* Bg = (const char*)(g_cb_h + ((size_t)dep * K + (size_t)candBase) * D);

    const int r0 = tid >> 3, j0 = tid & 7;
    uint32_t sdst[4];
#pragma unroll
    for (int i = 0; i < 4; i++) sdst[i] = swz((uint32_t)(r0 + i * 32) * 128u + j0 * 16u);
    const uint32_t gOff = (uint32_t)r0 * 512u + (uint32_t)j0 * 16u;

    float acc[2][8][4];
#pragma unroll
    for (int a = 0; a < 2; a++)
#pragma unroll
        for (int b = 0; b < 8; b++)
#pragma unroll
            for (int c = 0; c < 4; c++) acc[a][b][c] = 0.f;

    float d1[4] = {FLT_BIG, FLT_BIG, FLT_BIG, FLT_BIG};
    float d2[4] = {FLT_BIG, FLT_BIG, FLT_BIG, FLT_BIG};
    int   i1[4] = {0, 0, 0, 0}, i2[4] = {0, 0, 0, 0};

    const uint32_t aLin0 = (uint32_t)((wm * 32 + (lane & 15)) * 128 + (lane >> 4) * 16);
    const uint32_t aLin1 = aLin0 + 16 * 128;
    const uint32_t bLin  = (uint32_t)((wn * 64 + (lane & 7) + ((lane >> 4) << 3)) * 128 +
                                      ((lane >> 3) & 1) * 16);
    const float* cc = g_cc + (size_t)dep * K;
    const int thColBase = candBase + wn * 64 + (lane & 3) * 2;

    // prologue: group0 = all of A (4 chunk tiles) + B(0); group1 = B(1)
#pragma unroll
    for (int chA = 0; chA < 4; chA++)
#pragma unroll
        for (int i = 0; i < 4; i++)
            cpa16(sb + chA * TILE16 + sdst[i],
                  Ag + gOff + i * 32u * 512u + chA * 128u);
#pragma unroll
    for (int i = 0; i < 4; i++)
        cpa16(sb + SM_B + sdst[i], Bg + gOff + i * 32u * 512u);
    CP_COMMIT();
#pragma unroll
    for (int i = 0; i < 4; i++)
        cpa16(sb + SM_B + TILE16 + sdst[i], Bg + gOff + i * 32u * 512u + 128u);
    CP_COMMIT();

#pragma unroll
    for (int it = 0; it < 8; it++) {
        if (it < 7) { CP_WAIT(1); } else { CP_WAIT(0); }
        __syncthreads();

        if (it + 2 < 8) {
            const int itn = it + 2;
            const uint32_t bsrc = (uint32_t)(itn >> 2) * 65536u + (uint32_t)(itn & 3) * 128u;
            const uint32_t bstg = SM_B + (uint32_t)(itn % NBSTG) * TILE16;
#pragma unroll
            for (int i = 0; i < 4; i++)
                cpa16(sb + bstg + sdst[i], Bg + gOff + i * 32u * 512u + bsrc);
            CP_COMMIT();
        }

        const uint32_t aTile = sb + (uint32_t)(it & 3) * TILE16;
        const uint32_t bTile = sb + SM_B + (uint32_t)(it % NBSTG) * TILE16;
#pragma unroll
        for (int ks = 0; ks < 4; ks++) {
            uint32_t A0[4], A1[4], Bf[4][4];
            LDSM4(A0[0], A0[1], A0[2], A0[3], aTile + swz(aLin0 + ks * 32));
            LDSM4(A1[0], A1[1], A1[2], A1[3], aTile + swz(aLin1 + ks * 32));
#pragma unroll
            for (int nb = 0; nb < 4; nb++)
                LDSM4(Bf[nb][0], Bf[nb][1], Bf[nb][2], Bf[nb][3],
                      bTile + swz(bLin + nb * 16 * 128 + ks * 32));
#pragma unroll
            for (int nb = 0; nb < 4; nb++) {
                MMA16816(acc[0][nb * 2 + 0], A0, Bf[nb][0], Bf[nb][1]);
                MMA16816(acc[0][nb * 2 + 1], A0, Bf[nb][2], Bf[nb][3]);
                MMA16816(acc[1][nb * 2 + 0], A1, Bf[nb][0], Bf[nb][1]);
                MMA16816(acc[1][nb * 2 + 1], A1, Bf[nb][2], Bf[nb][3]);
            }
        }

        if ((it & 3) == 3)   // finished a 128-col sub-tile (ct = it>>2)
            consume_acc(acc, cc, thColBase + (it >> 2) * 128, d1, d2, i1, i2);
    }

    // final pack + merge + store (sTop aliases A tile 0; all reads done)
    __syncthreads();
    unsigned long long* sTop = (unsigned long long*)smem;   // [128][2][2]
#pragma unroll
    for (int s = 0; s < 4; s++) {
        unsigned long long b1 =
            ((unsigned long long)f2ord(d1[s]) << 32) | (unsigned int)i1[s];
        unsigned long long b2 =
            ((unsigned long long)f2ord(d2[s]) << 32) | (unsigned int)i2[s];
#pragma unroll
        for (int off = 1; off <= 2; off <<= 1) {
            unsigned long long o1 = __shfl_xor_sync(0xffffffffu, b1, off);
            unsigned long long o2 = __shfl_xor_sync(0xffffffffu, b2, off);
            merge2(b1, b2, o1, o2);
        }
        if ((lane & 3) == 0) {
            int rl = wm * 32 + (s >> 1) * 16 + (s & 1) * 8 + (lane >> 2);
            sTop[(rl * 2 + wn) * 2 + 0] = b1;
            sTop[(rl * 2 + wn) * 2 + 1] = b2;
        }
    }
    __syncthreads();
    if (tid < 128) {
        unsigned long long p1 = sTop[(tid * 2 + 0) * 2 + 0];
        unsigned long long p2 = sTop[(tid * 2 + 0) * 2 + 1];
        merge2(p1, p2, sTop[(tid * 2 + 1) * 2 + 0], sTop[(tid * 2 + 1) * 2 + 1]);
        size_t go = (size_t)(rowBase + tid) * 64 + blockIdx.y * 2;
        g_top[go + 0] = p1;
        g_top[go + 1] = p2;
    }
}

// ---------------- fused select + rescore + update: warp per row ----------------
// grid = N_ROWS/8 = 1024, block = 256 (8 warps)
__global__ void __launch_bounds__(256) k_finish(
        const float* __restrict__ x, const float* __restrict__ cb,
        float* __restrict__ out, float* __restrict__ codes,
        float* __restrict__ loss, int dep) {
    const int w = threadIdx.x >> 5, lane = threadIdx.x & 31;
    const int row = blockIdx.x * 8 + w;
    __shared__ unsigned long long se[8][64];
    __shared__ int sql[8][64];
    __shared__ float wloss[8];

    const unsigned long long* gt = g_top + (size_t)row * 64;
    unsigned long long b1 = ~0ull, b2 = ~0ull;
#pragma unroll
    for (int i = 0; i < 2; i++) {
        unsigned long long e = gt[lane + i * 32];
        se[w][lane + i * 32] = e;
        push2(b1, b2, e);
    }
#pragma unroll
    for (int off = 16; off > 0; off >>= 1) {
        unsigned long long o1 = __shfl_xor_sync(0xffffffffu, b1, off);
        unsigned long long o2 = __shfl_xor_sync(0xffffffffu, b2, off);
        merge2(b1, b2, o1, o2);
    }
    float d1 = ord2f((unsigned int)(b1 >> 32));
    float d2 = ord2f((unsigned int)(b2 >> 32));
    int idx = (int)(b1 & 0xFFFFFFFFu);

    const float4* rr = (const float4*)(g_res + (size_t)row * D);
    float4 r0 = rr[lane * 2], r1 = rr[lane * 2 + 1];

    if (d2 - d1 < MARGIN) {
        const float thr = d1 + MARGIN;
        int nq = 0;
        __syncwarp();
#pragma unroll
        for (int i = 0; i < 2; i++) {
            unsigned long long e = se[w][lane + i * 32];
            bool qf = ord2f((unsigned int)(e >> 32)) <= thr;
            unsigned m = __ballot_sync(0xffffffffu, qf);
            if (qf) {
                int pos = nq + __popc(m & ((1u << lane) - 1u));
                sql[w][pos] = (int)(e & 0xFFFFFFFFu);
            }
            nq += __popc(m);
        }
        __syncwarp();
        unsigned long long best = ~0ull;
        const float* ccd = g_cc + (size_t)dep * K;
        for (int q = 0; q < nq; q++) {
            int cand = sql[w][q];
            const float4* cr = (const float4*)(cb + (size_t)cand * D);
            float4 c0 = cr[lane * 2], c1 = cr[lane * 2 + 1];
            float p = r0.x * c0.x + r0.y * c0.y + r0.z * c0.z + r0.w * c0.w
                    + r1.x * c1.x + r1.y * c1.y + r1.z * c1.z + r1.w * c1.w;
#pragma unroll
            for (int o = 16; o > 0; o >>= 1) p += __shfl_xor_sync(0xffffffffu, p, o);
            float dist = ccd[cand] - 2.f * p;
            unsigned long long key =
                ((unsigned long long)f2ord(dist) << 32) | (unsigned int)cand;
            if (key < best) best = key;
        }
        idx = (int)(best & 0xFFFFFFFFu);
    }

    const size_t o4 = (size_t)row * (D / 4) + lane * 2;
    const float4* cbv = (const float4*)(cb + (size_t)idx * D);
    float4 q0 = cbv[lane * 2], q1 = cbv[lane * 2 + 1];
    float4 a0 = ((const float4*)g_agg)[o4], a1 = ((const float4*)g_agg)[o4 + 1];
    a0.x += q0.x; a0.y += q0.y; a0.z += q0.z; a0.w += q0.w;
    a1.x += q1.x; a1.y += q1.y; a1.z += q1.z; a1.w += q1.w;
    float4 x0 = ((const float4*)x)[o4], x1 = ((const float4*)x)[o4 + 1];

    if (dep < DEPTH - 1) {
        float4 n0, n1;
        n0.x = r0.x - q0.x; n0.y = r0.y - q0.y; n0.z = r0.z - q0.z; n0.w = r0.w - q0.w;
        n1.x = r1.x - q1.x; n1.y = r1.y - q1.y; n1.z = r1.z - q1.z; n1.w = r1.w - q1.w;
        ((float4*)g_res)[o4] = n0;
        ((float4*)g_res)[o4 + 1] = n1;
        uint4 hh;
        hh.x = h2_as_u32(__float22half2_rn(make_float2(n0.x, n0.y)));
        hh.y = h2_as_u32(__float22half2_rn(make_float2(n0.z, n0.w)));
        hh.z = h2_as_u32(__float22half2_rn(make_float2(n1.x, n1.y)));
        hh.w = h2_as_u32(__float22half2_rn(make_float2(n1.z, n1.w)));
        *(uint4*)(g_res_h + (size_t)row * D + lane * 8) = hh;
        ((float4*)g_agg)[o4] = a0;
        ((float4*)g_agg)[o4 + 1] = a1;
    } else {
        float4 ov0, ov1;
        ov0.x = x0.x + (a0.x - x0.x); ov0.y = x0.y + (a0.y - x0.y);
        ov0.z = x0.z + (a0.z - x0.z); ov0.w = x0.w + (a0.w - x0.w);
        ov1.x = x1.x + (a1.x - x1.x); ov1.y = x1.y + (a1.y - x1.y);
        ov1.z = x1.z + (a1.z - x1.z); ov1.w = x1.w + (a1.w - x1.w);
        ((float4*)out)[o4] = ov0;
        ((float4*)out)[o4 + 1] = ov1;
    }

    float d0x = x0.x - a0.x, d0y = x0.y - a0.y, d0z = x0.z - a0.z, d0w = x0.w - a0.w;
    float d1x = x1.x - a1.x, d1y = x1.y - a1.y, d1z = x1.z - a1.z, d1w = x1.w - a1.w;
    float s2 = d0x * d0x + d0y * d0y + d0z * d0z + d0w * d0w
             + d1x * d1x + d1y * d1y + d1z * d1z + d1w * d1w;
#pragma unroll
    for (int o = 16; o > 0; o >>= 1) s2 += __shfl_down_sync(0xffffffffu, s2, o);
    if (lane == 0) {
        wloss[w] = s2;
        codes[(size_t)row * DEPTH + dep] = (float)idx;
    }
    __syncthreads();
    if (threadIdx.x == 0) {
        float t = 0.f;
#pragma unroll
        for (int i = 0; i < 8; i++) t += wloss[i];
        atomicAdd(loss, t * LOSS_SCALE);
    }
}

extern "C" void kernel_launch(void* const* d_in, const int* in_sizes, int n_in,
                              void* d_out, int out_size) {
    const float* x = (const float*)d_in[0];
    const float* cbs = (const float*)d_in[1];
    float* out = (float*)d_out;
    float* loss = out + (size_t)N_ROWS * D;
    float* codes = loss + 1;

    cudaFuncSetAttribute(k_gemm, cudaFuncAttributeMaxDynamicSharedMemorySize, SMEMT);

    k_init<<<(N_ROWS * D + 255) / 256, 256>>>(x, loss);
    k_cb<<<DEPTH * K, 256>>>(cbs);

    for (int d = 0; d < DEPTH; d++) {
        const float* cb = cbs + (size_t)d * CB_STRIDE;
        dim3 grid(N_ROWS / BM, K / 256);
        k_gemm<<<grid, 256, SMEMT>>>(d);
        k_finish<<<N_ROWS / 8, 256>>>(x, cb, out, codes, loss, d);
    }
}

// round 16
// speedup vs baseline: 1.2974x; 1.0151x over previous
#include <cuda_runtime.h>
#include <cuda_fp16.h>
#include <cstdint>

#define N_ROWS 8192
#define D      256
#define K      8192
#define DEPTH  4
#define CB_STRIDE ((K + 1) * D)
#define LOSS_SCALE (0.25f / (4.0f * 2097152.0f))
#define MARGIN 8e-3f
#define FLT_BIG 3.402823466e38f

#define BM 128
#define TILE16 16384                 // 128 rows x 128B, pad-free (XOR swizzle)
#define SM_B  (4 * TILE16)           // A resident: 4 chunk tiles = 65536
#define NBSTG 3
#define SMEMT (SM_B + NBSTG * TILE16)   // 114688 -> 2 CTAs/SM

// ---------------- persistent scratch ----------------
__device__ __align__(256) float  g_res[N_ROWS * D];
__device__ __align__(256) __half g_res_h[N_ROWS * D];
__device__ __align__(256) __half g_cb_h[DEPTH * K * D];
__device__ __align__(16)  float  g_cc[DEPTH * K];
__device__ __align__(16)  unsigned long long g_top[N_ROWS * 64];   // 32 tiles x top-2

// ---------------- helpers ----------------
__device__ __forceinline__ uint32_t smem_u32(const void* p) {
    uint32_t a;
    asm("{ .reg .u64 t; cvta.to.shared.u64 t, %1; cvt.u32.u64 %0, t; }" : "=r"(a) : "l"(p));
    return a;
}
__device__ __forceinline__ uint32_t swz(uint32_t x) { return x ^ ((x >> 3) & 0x70u); }
__device__ __forceinline__ uint32_t h2_as_u32(__half2 h) {
    return *reinterpret_cast<uint32_t*>(&h);
}
__device__ __forceinline__ unsigned int f2ord(float f) {
    unsigned int u = __float_as_uint(f);
    return (u & 0x80000000u) ? ~u : (u | 0x80000000u);
}
__device__ __forceinline__ float ord2f(unsigned int o) {
    unsigned int u = (o & 0x80000000u) ? (o & 0x7FFFFFFFu) : ~o;
    return __uint_as_float(u);
}
__device__ __forceinline__ void merge2(unsigned long long& b1, unsigned long long& b2,
                                       unsigned long long o1, unsigned long long o2) {
    if (o1 < b1) { b2 = (b1 < o2) ? b1 : o2; b1 = o1; }
    else if (o1 < b2) { b2 = o1; }
}
__device__ __forceinline__ void push2(unsigned long long& b1, unsigned long long& b2,
                                      unsigned long long k) {
    if (k < b1) { b2 = b1; b1 = k; }
    else if (k < b2) { b2 = k; }
}

__device__ __forceinline__ void cpa16(uint32_t dst, const void* src) {
    asm volatile("cp.async.cg.shared.global [%0], [%1], 16;" :: "r"(dst), "l"(src));
}
#define CP_COMMIT() asm volatile("cp.async.commit_group;" ::: "memory")
#define CP_WAIT(n)  asm volatile("cp.async.wait_group %0;" :: "n"(n) : "memory")

#define LDSM4(r0, r1, r2, r3, a) \
    asm volatile("ldmatrix.sync.aligned.m8n8.x4.shared.b16 {%0,%1,%2,%3}, [%4];" \
                 : "=r"(r0), "=r"(r1), "=r"(r2), "=r"(r3) : "r"(a))

#define MMA16816(c, a, b0, b1) \
    asm volatile("mma.sync.aligned.m16n8k16.row.col.f32.f16.f16.f32 " \
                 "{%0,%1,%2,%3},{%4,%5,%6,%7},{%8,%9},{%0,%1,%2,%3};" \
                 : "+f"((c)[0]), "+f"((c)[1]), "+f"((c)[2]), "+f"((c)[3]) \
                 : "r"((a)[0]), "r"((a)[1]), "r"((a)[2]), "r"((a)[3]), "r"(b0), "r"(b1))

// reduce two values across a 256-thread block; result in thread 0
__device__ __forceinline__ void blockReduce2_256(float& a, float& b) {
    __shared__ float sa[8], sb2[8];
    int lane = threadIdx.x & 31, w = threadIdx.x >> 5;
#pragma unroll
    for (int o = 16; o > 0; o >>= 1) {
        a += __shfl_down_sync(0xffffffffu, a, o);
        b += __shfl_down_sync(0xffffffffu, b, o);
    }
    if (lane == 0) { sa[w] = a; sb2[w] = b; }
    __syncthreads();
    if (w == 0) {
        a = (lane < 8) ? sa[lane] : 0.f;
        b = (lane < 8) ? sb2[lane] : 0.f;
#pragma unroll
        for (int o = 4; o > 0; o >>= 1) {
            a += __shfl_down_sync(0xffu, a, o);
            b += __shfl_down_sync(0xffu, b, o);
        }
    }
}

// ---------------- setup ----------------
__global__ void k_init(const float* __restrict__ x, float* __restrict__ loss) {
    int i = blockIdx.x * blockDim.x + threadIdx.x;
    if (i < N_ROWS * D) {
        float v = x[i];
        g_res[i] = v;
        g_res_h[i] = __float2half_rn(v);
    }
    if (i == 0) *loss = 0.f;
}

__global__ void k_cb(const float* __restrict__ cbs) {
    int rid = blockIdx.x;                     // 0 .. DEPTH*K-1
    int dd = rid / K, r = rid % K;
    float v = cbs[(size_t)dd * CB_STRIDE + (size_t)r * D + threadIdx.x];
    g_cb_h[(size_t)rid * D + threadIdx.x] = __float2half_rn(v);
    float a = v * v, b = 0.f;
    blockReduce2_256(a, b);
    if (threadIdx.x == 0) g_cc[rid] = a;
}

// consume one 128-col sub-tile's accumulators into running float top-2
__device__ __forceinline__ void consume_acc(
        float acc[2][8][4], const float* __restrict__ cc, int colBase,
        float d1[4], float d2[4], int i1[4], int i2[4]) {
#pragma unroll
    for (int mb = 0; mb < 2; mb++) {
#pragma unroll
        for (int rb = 0; rb < 2; rb++) {
            const int s = mb * 2 + rb;
#pragma unroll
            for (int nf = 0; nf < 8; nf++) {
                int col = colBase + nf * 8;
                float2 c2 = *(const float2*)&cc[col];
                float k0 = fmaf(-2.f, acc[mb][nf][rb * 2 + 0], c2.x);
                float k1 = fmaf(-2.f, acc[mb][nf][rb * 2 + 1], c2.y);
                if (k0 < d2[s]) {
                    if (k0 < d1[s]) { d2[s] = d1[s]; i2[s] = i1[s]; d1[s] = k0; i1[s] = col; }
                    else { d2[s] = k0; i2[s] = col; }
                }
                if (k1 < d2[s]) {
                    if (k1 < d1[s]) { d2[s] = d1[s]; i2[s] = i1[s]; d1[s] = k1; i1[s] = col + 1; }
                    else { d2[s] = k1; i2[s] = col + 1; }
                }
                acc[mb][nf][rb * 2 + 0] = 0.f;
                acc[mb][nf][rb * 2 + 1] = 0.f;
            }
        }
    }
}

// ---------------- HMMA GEMM + per-CTA top-2 (R10 configuration) ----------------
// grid = (64, 32), block = 256 (8 warps: 4 row x 2 col)
// A (128x256) resident (XOR-swizzled, pad-free); B streamed through 3 stages,
// prefetch distance 2 (CP_WAIT(1)).
__global__ void __launch_bounds__(256, 2) k_gemm(int dep) {
    extern __shared__ char smem[];
    const uint32_t sb = smem_u32(smem);
    const int tid = threadIdx.x, lane = tid & 31, wid = tid >> 5;
    const int wm = wid & 3, wn = wid >> 2;
    const int rowBase = blockIdx.x * BM, candBase = blockIdx.y * 256;

    const char* Ag = (const char*)(g_res_h + (size_t)rowBase * D);
    const char* Bg = (const char*)(g_cb_h + ((size_t)dep * K + (size_t)candBase) * D);

    const int r0 = tid >> 3, j0 = tid & 7;
    uint32_t sdst[4];
#pragma unroll
    for (int i = 0; i < 4; i++) sdst[i] = swz((uint32_t)(r0 + i * 32) * 128u + j0 * 16u);
    const uint32_t gOff = (uint32_t)r0 * 512u + (uint32_t)j0 * 16u;

    float acc[2][8][4];
#pragma unroll
    for (int a = 0; a < 2; a++)
#pragma unroll
        for (int b = 0; b < 8; b++)
#pragma unroll
            for (int c = 0; c < 4; c++) acc[a][b][c] = 0.f;

    float d1[4] = {FLT_BIG, FLT_BIG, FLT_BIG, FLT_BIG};
    float d2[4] = {FLT_BIG, FLT_BIG, FLT_BIG, FLT_BIG};
    int   i1[4] = {0, 0, 0, 0}, i2[4] = {0, 0, 0, 0};

    const uint32_t aLin0 = (uint32_t)((wm * 32 + (lane & 15)) * 128 + (lane >> 4) * 16);
    const uint32_t aLin1 = aLin0 + 16 * 128;
    const uint32_t bLin  = (uint32_t)((wn * 64 + (lane & 7) + ((lane >> 4) << 3)) * 128 +
                                      ((lane >> 3) & 1) * 16);
    const float* cc = g_cc + (size_t)dep * K;
    const int thColBase = candBase + wn * 64 + (lane & 3) * 2;

    // prologue: group0 = all of A (4 chunk tiles) + B(0); group1 = B(1)
#pragma unroll
    for (int chA = 0; chA < 4; chA++)
#pragma unroll
        for (int i = 0; i < 4; i++)
            cpa16(sb + chA * TILE16 + sdst[i],
                  Ag + gOff + i * 32u * 512u + chA * 128u);
#pragma unroll
    for (int i = 0; i < 4; i++)
        cpa16(sb + SM_B + sdst[i], Bg + gOff + i * 32u * 512u);
    CP_COMMIT();
#pragma unroll
    for (int i = 0; i < 4; i++)
        cpa16(sb + SM_B + TILE16 + sdst[i], Bg + gOff + i * 32u * 512u + 128u);
    CP_COMMIT();

#pragma unroll
    for (int it = 0; it < 8; it++) {
        if (it < 7) { CP_WAIT(1); } else { CP_WAIT(0); }
        __syncthreads();

        if (it + 2 < 8) {
            const int itn = it + 2;
            const uint32_t bsrc = (uint32_t)(itn >> 2) * 65536u + (uint32_t)(itn & 3) * 128u;
            const uint32_t bstg = SM_B + (uint32_t)(itn % NBSTG) * TILE16;
#pragma unroll
            for (int i = 0; i < 4; i++)
                cpa16(sb + bstg + sdst[i], Bg + gOff + i * 32u * 512u + bsrc);
            CP_COMMIT();
        }

        const uint32_t aTile = sb + (uint32_t)(it & 3) * TILE16;
        const uint32_t bTile = sb + SM_B + (uint32_t)(it % NBSTG) * TILE16;
#pragma unroll
        for (int ks = 0; ks < 4; ks++) {
            uint32_t A0[4], A1[4], Bf[4][4];
            LDSM4(A0[0], A0[1], A0[2], A0[3], aTile + swz(aLin0 + ks * 32));
            LDSM4(A1[0], A1[1], A1[2], A1[3], aTile + swz(aLin1 + ks * 32));
#pragma unroll
            for (int nb = 0; nb < 4; nb++)
                LDSM4(Bf[nb][0], Bf[nb][1], Bf[nb][2], Bf[nb][3],
                      bTile + swz(bLin + nb * 16 * 128 + ks * 32));
#pragma unroll
            for (int nb = 0; nb < 4; nb++) {
                MMA16816(acc[0][nb * 2 + 0], A0, Bf[nb][0], Bf[nb][1]);
                MMA16816(acc[0][nb * 2 + 1], A0, Bf[nb][2], Bf[nb][3]);
                MMA16816(acc[1][nb * 2 + 0], A1, Bf[nb][0], Bf[nb][1]);
                MMA16816(acc[1][nb * 2 + 1], A1, Bf[nb][2], Bf[nb][3]);
            }
        }

        if ((it & 3) == 3)   // finished a 128-col sub-tile (ct = it>>2)
            consume_acc(acc, cc, thColBase + (it >> 2) * 128, d1, d2, i1, i2);
    }

    // final pack + merge + store (sTop aliases A tile 0; all reads done)
    __syncthreads();
    unsigned long long* sTop = (unsigned long long*)smem;   // [128][2][2]
#pragma unroll
    for (int s = 0; s < 4; s++) {
        unsigned long long b1 =
            ((unsigned long long)f2ord(d1[s]) << 32) | (unsigned int)i1[s];
        unsigned long long b2 =
            ((unsigned long long)f2ord(d2[s]) << 32) | (unsigned int)i2[s];
#pragma unroll
        for (int off = 1; off <= 2; off <<= 1) {
            unsigned long long o1 = __shfl_xor_sync(0xffffffffu, b1, off);
            unsigned long long o2 = __shfl_xor_sync(0xffffffffu, b2, off);
            merge2(b1, b2, o1, o2);
        }
        if ((lane & 3) == 0) {
            int rl = wm * 32 + (s >> 1) * 16 + (s & 1) * 8 + (lane >> 2);
            sTop[(rl * 2 + wn) * 2 + 0] = b1;
            sTop[(rl * 2 + wn) * 2 + 1] = b2;
        }
    }
    __syncthreads();
    if (tid < 128) {
        unsigned long long p1 = sTop[(tid * 2 + 0) * 2 + 0];
        unsigned long long p2 = sTop[(tid * 2 + 0) * 2 + 1];
        merge2(p1, p2, sTop[(tid * 2 + 1) * 2 + 0], sTop[(tid * 2 + 1) * 2 + 1]);
        size_t go = (size_t)(rowBase + tid) * 64 + blockIdx.y * 2;
        g_top[go + 0] = p1;
        g_top[go + 1] = p2;
    }
}

// ---------------- fused select + rescore + update: warp per row ----------------
// grid = N_ROWS/8 = 1024, block = 256 (8 warps). agg eliminated: agg = x - res.
__global__ void __launch_bounds__(256) k_finish(
        const float* __restrict__ x, const float* __restrict__ cb,
        float* __restrict__ out, float* __restrict__ codes,
        float* __restrict__ loss, int dep) {
    const int w = threadIdx.x >> 5, lane = threadIdx.x & 31;
    const int row = blockIdx.x * 8 + w;
    __shared__ unsigned long long se[8][64];
    __shared__ int sql[8][64];
    __shared__ float wloss[8];

    const unsigned long long* gt = g_top + (size_t)row * 64;
    unsigned long long b1 = ~0ull, b2 = ~0ull;
#pragma unroll
    for (int i = 0; i < 2; i++) {
        unsigned long long e = gt[lane + i * 32];
        se[w][lane + i * 32] = e;
        push2(b1, b2, e);
    }
#pragma unroll
    for (int off = 16; off > 0; off >>= 1) {
        unsigned long long o1 = __shfl_xor_sync(0xffffffffu, b1, off);
        unsigned long long o2 = __shfl_xor_sync(0xffffffffu, b2, off);
        merge2(b1, b2, o1, o2);
    }
    float d1 = ord2f((unsigned int)(b1 >> 32));
    float d2 = ord2f((unsigned int)(b2 >> 32));
    int idx = (int)(b1 & 0xFFFFFFFFu);

    const float4* rr = (const float4*)(g_res + (size_t)row * D);
    float4 r0 = rr[lane * 2], r1 = rr[lane * 2 + 1];

    if (d2 - d1 < MARGIN) {
        const float thr = d1 + MARGIN;
        int nq = 0;
        __syncwarp();
#pragma unroll
        for (int i = 0; i < 2; i++) {
            unsigned long long e = se[w][lane + i * 32];
            bool qf = ord2f((unsigned int)(e >> 32)) <= thr;
            unsigned m = __ballot_sync(0xffffffffu, qf);
            if (qf) {
                int pos = nq + __popc(m & ((1u << lane) - 1u));
                sql[w][pos] = (int)(e & 0xFFFFFFFFu);
            }
            nq += __popc(m);
        }
        __syncwarp();
        unsigned long long best = ~0ull;
        const float* ccd = g_cc + (size_t)dep * K;
        for (int q = 0; q < nq; q++) {
            int cand = sql[w][q];
            const float4* cr = (const float4*)(cb + (size_t)cand * D);
            float4 c0 = cr[lane * 2], c1 = cr[lane * 2 + 1];
            float p = r0.x * c0.x + r0.y * c0.y + r0.z * c0.z + r0.w * c0.w
                    + r1.x * c1.x + r1.y * c1.y + r1.z * c1.z + r1.w * c1.w;
#pragma unroll
            for (int o = 16; o > 0; o >>= 1) p += __shfl_xor_sync(0xffffffffu, p, o);
            float dist = ccd[cand] - 2.f * p;
            unsigned long long key =
                ((unsigned long long)f2ord(dist) << 32) | (unsigned int)cand;
            if (key < best) best = key;
        }
        idx = (int)(best & 0xFFFFFFFFu);
    }

    // ---- update: each lane owns 8 contiguous elements; agg = x - res ----
    const size_t o4 = (size_t)row * (D / 4) + lane * 2;
    const float4* cbv = (const float4*)(cb + (size_t)idx * D);
    float4 q0 = cbv[lane * 2], q1 = cbv[lane * 2 + 1];
    float4 x0 = ((const float4*)x)[o4], x1 = ((const float4*)x)[o4 + 1];

    float4 n0, n1;
    n0.x = r0.x - q0.x; n0.y = r0.y - q0.y; n0.z = r0.z - q0.z; n0.w = r0.w - q0.w;
    n1.x = r1.x - q1.x; n1.y = r1.y - q1.y; n1.z = r1.z - q1.z; n1.w = r1.w - q1.w;

    // a = x - r_new  (aggregate), diff = x - a
    float4 a0, a1;
    a0.x = x0.x - n0.x; a0.y = x0.y - n0.y; a0.z = x0.z - n0.z; a0.w = x0.w - n0.w;
    a1.x = x1.x - n1.x; a1.y = x1.y - n1.y; a1.z = x1.z - n1.z; a1.w = x1.w - n1.w;

    if (dep < DEPTH - 1) {
        ((float4*)g_res)[o4] = n0;
        ((float4*)g_res)[o4 + 1] = n1;
        uint4 hh;
        hh.x = h2_as_u32(__float22half2_rn(make_float2(n0.x, n0.y)));
        hh.y = h2_as_u32(__float22half2_rn(make_float2(n0.z, n0.w)));
        hh.z = h2_as_u32(__float22half2_rn(make_float2(n1.x, n1.y)));
        hh.w = h2_as_u32(__float22half2_rn(make_float2(n1.z, n1.w)));
        *(uint4*)(g_res_h + (size_t)row * D + lane * 8) = hh;
    } else {
        float4 ov0, ov1;
        ov0.x = x0.x + (a0.x - x0.x); ov0.y = x0.y + (a0.y - x0.y);
        ov0.z = x0.z + (a0.z - x0.z); ov0.w = x0.w + (a0.w - x0.w);
        ov1.x = x1.x + (a1.x - x1.x); ov1.y = x1.y + (a1.y - x1.y);
        ov1.z = x1.z + (a1.z - x1.z); ov1.w = x1.w + (a1.w - x1.w);
        ((float4*)out)[o4] = ov0;
        ((float4*)out)[o4 + 1] = ov1;
    }

    float d0x = x0.x - a0.x, d0y = x0.y - a0.y, d0z = x0.z - a0.z, d0w = x0.w - a0.w;
    float d1x = x1.x - a1.x, d1y = x1.y - a1.y, d1z = x1.z - a1.z, d1w = x1.w - a1.w;
    float s2 = d0x * d0x + d0y * d0y + d0z * d0z + d0w * d0w
             + d1x * d1x + d1y * d1y + d1z * d1z + d1w * d1w;
#pragma unroll
    for (int o = 16; o > 0; o >>= 1) s2 += __shfl_down_sync(0xffffffffu, s2, o);
    if (lane == 0) {
        wloss[w] = s2;
        codes[(size_t)row * DEPTH + dep] = (float)idx;
    }
    __syncthreads();
    if (threadIdx.x == 0) {
        float t = 0.f;
#pragma unroll
        for (int i = 0; i < 8; i++) t += wloss[i];
        atomicAdd(loss, t * LOSS_SCALE);
    }
}

extern "C" void kernel_launch(void* const* d_in, const int* in_sizes, int n_in,
                              void* d_out, int out_size) {
    const float* x = (const float*)d_in[0];
    const float* cbs = (const float*)d_in[1];
    float* out = (float*)d_out;
    float* loss = out + (size_t)N_ROWS * D;
    float* codes = loss + 1;

    cudaFuncSetAttribute(k_gemm, cudaFuncAttributeMaxDynamicSharedMemorySize, SMEMT);

    k_init<<<(N_ROWS * D + 255) / 256, 256>>>(x, loss);
    k_cb<<<DEPTH * K, 256>>>(cbs);

    for (int d = 0; d < DEPTH; d++) {
        const float* cb = cbs + (size_t)d * CB_STRIDE;
        dim3 grid(N_ROWS / BM, K / 256);
        k_gemm<<<grid, 256, SMEMT>>>(d);
        k_finish<<<N_ROWS / 8, 256>>>(x, cb, out, codes, loss, d);
    }
}

// round 17
// speedup vs baseline: 1.3235x; 1.0201x over previous
#include <cuda_runtime.h>
#include <cuda_fp16.h>
#include <cstdint>

#define N_ROWS 8192
#define D      256
#define K      8192
#define DEPTH  4
#define CB_STRIDE ((K + 1) * D)
#define LOSS_SCALE (0.25f / (4.0f * 2097152.0f))
#define MARGIN 8e-3f
#define FLT_BIG 3.402823466e38f

#define BM 128
#define TILE16 16384                 // 128 rows x 128B, pad-free (XOR swizzle)
#define SM_B  (4 * TILE16)           // A resident: 4 chunk tiles = 65536
#define NBSTG 3
#define SMEMT (SM_B + NBSTG * TILE16)   // 114688 -> 2 CTAs/SM

// ---------------- persistent scratch ----------------
__device__ __align__(256) float  g_res[N_ROWS * D];
__device__ __align__(256) __half g_res_h[N_ROWS * D];
__device__ __align__(256) __half g_cb_h[DEPTH * K * D];
__device__ __align__(16)  float  g_cc[DEPTH * K];
__device__ __align__(16)  unsigned long long g_top[N_ROWS * 64];   // 32 tiles x top-2

// ---------------- helpers ----------------
__device__ __forceinline__ uint32_t smem_u32(const void* p) {
    uint32_t a;
    asm("{ .reg .u64 t; cvta.to.shared.u64 t, %1; cvt.u32.u64 %0, t; }" : "=r"(a) : "l"(p));
    return a;
}
__device__ __forceinline__ uint32_t swz(uint32_t x) { return x ^ ((x >> 3) & 0x70u); }
__device__ __forceinline__ uint32_t h2_as_u32(__half2 h) {
    return *reinterpret_cast<uint32_t*>(&h);
}
__device__ __forceinline__ unsigned int f2ord(float f) {
    unsigned int u = __float_as_uint(f);
    return (u & 0x80000000u) ? ~u : (u | 0x80000000u);
}
__device__ __forceinline__ float ord2f(unsigned int o) {
    unsigned int u = (o & 0x80000000u) ? (o & 0x7FFFFFFFu) : ~o;
    return __uint_as_float(u);
}
__device__ __forceinline__ void merge2(unsigned long long& b1, unsigned long long& b2,
                                       unsigned long long o1, unsigned long long o2) {
    if (o1 < b1) { b2 = (b1 < o2) ? b1 : o2; b1 = o1; }
    else if (o1 < b2) { b2 = o1; }
}
__device__ __forceinline__ void push2(unsigned long long& b1, unsigned long long& b2,
                                      unsigned long long k) {
    if (k < b1) { b2 = b1; b1 = k; }
    else if (k < b2) { b2 = k; }
}

__device__ __forceinline__ void cpa16(uint32_t dst, const void* src) {
    asm volatile("cp.async.cg.shared.global [%0], [%1], 16;" :: "r"(dst), "l"(src));
}
#define CP_COMMIT() asm volatile("cp.async.commit_group;" ::: "memory")
#define CP_WAIT(n)  asm volatile("cp.async.wait_group %0;" :: "n"(n) : "memory")

#define LDSM4(r0, r1, r2, r3, a) \
    asm volatile("ldmatrix.sync.aligned.m8n8.x4.shared.b16 {%0,%1,%2,%3}, [%4];" \
                 : "=r"(r0), "=r"(r1), "=r"(r2), "=r"(r3) : "r"(a))

#define MMA16816(c, a, b0, b1) \
    asm volatile("mma.sync.aligned.m16n8k16.row.col.f32.f16.f16.f32 " \
                 "{%0,%1,%2,%3},{%4,%5,%6,%7},{%8,%9},{%0,%1,%2,%3};" \
                 : "+f"((c)[0]), "+f"((c)[1]), "+f"((c)[2]), "+f"((c)[3]) \
                 : "r"((a)[0]), "r"((a)[1]), "r"((a)[2]), "r"((a)[3]), "r"(b0), "r"(b1))

// ---------------- setup (vectorized) ----------------
// grid-stride float4 copy + half conversion; one thread = 4 elements
__global__ void k_init(const float* __restrict__ x, float* __restrict__ loss) {
    int i = blockIdx.x * blockDim.x + threadIdx.x;      // 0 .. N_ROWS*D/4-1
    float4 v = ((const float4*)x)[i];
    ((float4*)g_res)[i] = v;
    uint2 hh;
    hh.x = h2_as_u32(__float22half2_rn(make_float2(v.x, v.y)));
    hh.y = h2_as_u32(__float22half2_rn(make_float2(v.z, v.w)));
    ((uint2*)g_res_h)[i] = hh;
    if (i == 0) *loss = 0.f;
}

// one 64-thread block per codebook row: float4 load, uint2 store, warp+smem reduce
__global__ void __launch_bounds__(64) k_cb(const float* __restrict__ cbs) {
    __shared__ float sred[2];
    const int rid = blockIdx.x;               // 0 .. DEPTH*K-1
    const int dd = rid >> 13, r = rid & (K - 1);
    const int t = threadIdx.x, lane = t & 31, w = t >> 5;

    const float4* src = (const float4*)(cbs + (size_t)dd * CB_STRIDE + (size_t)r * D);
    float4 v = src[t];
    uint2 hh;
    hh.x = h2_as_u32(__float22half2_rn(make_float2(v.x, v.y)));
    hh.y = h2_as_u32(__float22half2_rn(make_float2(v.z, v.w)));
    ((uint2*)(g_cb_h + (size_t)rid * D))[t] = hh;

    float a = v.x * v.x + v.y * v.y + v.z * v.z + v.w * v.w;
#pragma unroll
    for (int o = 16; o > 0; o >>= 1) a += __shfl_down_sync(0xffffffffu, a, o);
    if (lane == 0) sred[w] = a;
    __syncthreads();
    if (t == 0) g_cc[rid] = sred[0] + sred[1];
}

// consume one 128-col sub-tile's accumulators into running float top-2
__device__ __forceinline__ void consume_acc(
        float acc[2][8][4], const float* __restrict__ cc, int colBase,
        float d1[4], float d2[4], int i1[4], int i2[4]) {
#pragma unroll
    for (int mb = 0; mb < 2; mb++) {
#pragma unroll
        for (int rb = 0; rb < 2; rb++) {
            const int s = mb * 2 + rb;
#pragma unroll
            for (int nf = 0; nf < 8; nf++) {
                int col = colBase + nf * 8;
                float2 c2 = *(const float2*)&cc[col];
                float k0 = fmaf(-2.f, acc[mb][nf][rb * 2 + 0], c2.x);
                float k1 = fmaf(-2.f, acc[mb][nf][rb * 2 + 1], c2.y);
                if (k0 < d2[s]) {
                    if (k0 < d1[s]) { d2[s] = d1[s]; i2[s] = i1[s]; d1[s] = k0; i1[s] = col; }
                    else { d2[s] = k0; i2[s] = col; }
                }
                if (k1 < d2[s]) {
                    if (k1 < d1[s]) { d2[s] = d1[s]; i2[s] = i1[s]; d1[s] = k1; i1[s] = col + 1; }
                    else { d2[s] = k1; i2[s] = col + 1; }
                }
                acc[mb][nf][rb * 2 + 0] = 0.f;
                acc[mb][nf][rb * 2 + 1] = 0.f;
            }
        }
    }
}

// ---------------- HMMA GEMM + per-CTA top-2 (R10 configuration) ----------------
// grid = (64, 32), block = 256 (8 warps: 4 row x 2 col)
__global__ void __launch_bounds__(256, 2) k_gemm(int dep) {
    extern __shared__ char smem[];
    const uint32_t sb = smem_u32(smem);
    const int tid = threadIdx.x, lane = tid & 31, wid = tid >> 5;
    const int wm = wid & 3, wn = wid >> 2;
    const int rowBase = blockIdx.x * BM, candBase = blockIdx.y * 256;

    const char* Ag = (const char*)(g_res_h + (size_t)rowBase * D);
    const char* Bg = (const char*)(g_cb_h + ((size_t)dep * K + (size_t)candBase) * D);

    const int r0 = tid >> 3, j0 = tid & 7;
    uint32_t sdst[4];
#pragma unroll
    for (int i = 0; i < 4; i++) sdst[i] = swz((uint32_t)(r0 + i * 32) * 128u + j0 * 16u);
    const uint32_t gOff = (uint32_t)r0 * 512u + (uint32_t)j0 * 16u;

    float acc[2][8][4];
#pragma unroll
    for (int a = 0; a < 2; a++)
#pragma unroll
        for (int b = 0; b < 8; b++)
#pragma unroll
            for (int c = 0; c < 4; c++) acc[a][b][c] = 0.f;

    float d1[4] = {FLT_BIG, FLT_BIG, FLT_BIG, FLT_BIG};
    float d2[4] = {FLT_BIG, FLT_BIG, FLT_BIG, FLT_BIG};
    int   i1[4] = {0, 0, 0, 0}, i2[4] = {0, 0, 0, 0};

    const uint32_t aLin0 = (uint32_t)((wm * 32 + (lane & 15)) * 128 + (lane >> 4) * 16);
    const uint32_t aLin1 = aLin0 + 16 * 128;
    const uint32_t bLin  = (uint32_t)((wn * 64 + (lane & 7) + ((lane >> 4) << 3)) * 128 +
                                      ((lane >> 3) & 1) * 16);
    const float* cc = g_cc + (size_t)dep * K;
    const int thColBase = candBase + wn * 64 + (lane & 3) * 2;

    // prologue: group0 = all of A (4 chunk tiles) + B(0); group1 = B(1)
#pragma unroll
    for (int chA = 0; chA < 4; chA++)
#pragma unroll
        for (int i = 0; i < 4; i++)
            cpa16(sb + chA * TILE16 + sdst[i],
                  Ag + gOff + i * 32u * 512u + chA * 128u);
#pragma unroll
    for (int i = 0; i < 4; i++)
        cpa16(sb + SM_B + sdst[i], Bg + gOff + i * 32u * 512u);
    CP_COMMIT();
#pragma unroll
    for (int i = 0; i < 4; i++)
        cpa16(sb + SM_B + TILE16 + sdst[i], Bg + gOff + i * 32u * 512u + 128u);
    CP_COMMIT();

#pragma unroll
    for (int it = 0; it < 8; it++) {
        if (it < 7) { CP_WAIT(1); } else { CP_WAIT(0); }
        __syncthreads();

        if (it + 2 < 8) {
            const int itn = it + 2;
            const uint32_t bsrc = (uint32_t)(itn >> 2) * 65536u + (uint32_t)(itn & 3) * 128u;
            const uint32_t bstg = SM_B + (uint32_t)(itn % NBSTG) * TILE16;
#pragma unroll
            for (int i = 0; i < 4; i++)
                cpa16(sb + bstg + sdst[i], Bg + gOff + i * 32u * 512u + bsrc);
            CP_COMMIT();
        }

        const uint32_t aTile = sb + (uint32_t)(it & 3) * TILE16;
        const uint32_t bTile = sb + SM_B + (uint32_t)(it % NBSTG) * TILE16;
#pragma unroll
        for (int ks = 0; ks < 4; ks++) {
            uint32_t A0[4], A1[4], Bf[4][4];
            LDSM4(A0[0], A0[1], A0[2], A0[3], aTile + swz(aLin0 + ks * 32));
            LDSM4(A1[0], A1[1], A1[2], A1[3], aTile + swz(aLin1 + ks * 32));
#pragma unroll
            for (int nb = 0; nb < 4; nb++)
                LDSM4(Bf[nb][0], Bf[nb][1], Bf[nb][2], Bf[nb][3],
                      bTile + swz(bLin + nb * 16 * 128 + ks * 32));
#pragma unroll
            for (int nb = 0; nb < 4; nb++) {
                MMA16816(acc[0][nb * 2 + 0], A0, Bf[nb][0], Bf[nb][1]);
                MMA16816(acc[0][nb * 2 + 1], A0, Bf[nb][2], Bf[nb][3]);
                MMA16816(acc[1][nb * 2 + 0], A1, Bf[nb][0], Bf[nb][1]);
                MMA16816(acc[1][nb * 2 + 1], A1, Bf[nb][2], Bf[nb][3]);
            }
        }

        if ((it & 3) == 3)   // finished a 128-col sub-tile (ct = it>>2)
            consume_acc(acc, cc, thColBase + (it >> 2) * 128, d1, d2, i1, i2);
    }

    // final pack + merge + store (sTop aliases A tile 0; all reads done)
    __syncthreads();
    unsigned long long* sTop = (unsigned long long*)smem;   // [128][2][2]
#pragma unroll
    for (int s = 0; s < 4; s++) {
        unsigned long long b1 =
            ((unsigned long long)f2ord(d1[s]) << 32) | (unsigned int)i1[s];
        unsigned long long b2 =
            ((unsigned long long)f2ord(d2[s]) << 32) | (unsigned int)i2[s];
#pragma unroll
        for (int off = 1; off <= 2; off <<= 1) {
            unsigned long long o1 = __shfl_xor_sync(0xffffffffu, b1, off);
            unsigned long long o2 = __shfl_xor_sync(0xffffffffu, b2, off);
            merge2(b1, b2, o1, o2);
        }
        if ((lane & 3) == 0) {
            int rl = wm * 32 + (s >> 1) * 16 + (s & 1) * 8 + (lane >> 2);
            sTop[(rl * 2 + wn) * 2 + 0] = b1;
            sTop[(rl * 2 + wn) * 2 + 1] = b2;
        }
    }
    __syncthreads();
    if (tid < 128) {
        unsigned long long p1 = sTop[(tid * 2 + 0) * 2 + 0];
        unsigned long long p2 = sTop[(tid * 2 + 0) * 2 + 1];
        merge2(p1, p2, sTop[(tid * 2 + 1) * 2 + 0], sTop[(tid * 2 + 1) * 2 + 1]);
        size_t go = (size_t)(rowBase + tid) * 64 + blockIdx.y * 2;
        g_top[go + 0] = p1;
        g_top[go + 1] = p2;
    }
}

// ---------------- fused select + rescore + update: warp per row ----------------
// grid = N_ROWS/8 = 1024, block = 256 (8 warps). agg eliminated: agg = x - res.
__global__ void __launch_bounds__(256) k_finish(
        const float* __restrict__ x, const float* __restrict__ cb,
        float* __restrict__ out, float* __restrict__ codes,
        float* __restrict__ loss, int dep) {
    const int w = threadIdx.x >> 5, lane = threadIdx.x & 31;
    const int row = blockIdx.x * 8 + w;
    __shared__ unsigned long long se[8][64];
    __shared__ int sql[8][64];
    __shared__ float wloss[8];

    const unsigned long long* gt = g_top + (size_t)row * 64;
    unsigned long long b1 = ~0ull, b2 = ~0ull;
#pragma unroll
    for (int i = 0; i < 2; i++) {
        unsigned long long e = gt[lane + i * 32];
        se[w][lane + i * 32] = e;
        push2(b1, b2, e);
    }
#pragma unroll
    for (int off = 16; off > 0; off >>= 1) {
        unsigned long long o1 = __shfl_xor_sync(0xffffffffu, b1, off);
        unsigned long long o2 = __shfl_xor_sync(0xffffffffu, b2, off);
        merge2(b1, b2, o1, o2);
    }
    float d1 = ord2f((unsigned int)(b1 >> 32));
    float d2 = ord2f((unsigned int)(b2 >> 32));
    int idx = (int)(b1 & 0xFFFFFFFFu);

    const float4* rr = (const float4*)(g_res + (size_t)row * D);
    float4 r0 = rr[lane * 2], r1 = rr[lane * 2 + 1];

    if (d2 - d1 < MARGIN) {
        const float thr = d1 + MARGIN;
        int nq = 0;
        __syncwarp();
#pragma unroll
        for (int i = 0; i < 2; i++) {
            unsigned long long e = se[w][lane + i * 32];
            bool qf = ord2f((unsigned int)(e >> 32)) <= thr;
            unsigned m = __ballot_sync(0xffffffffu, qf);
            if (qf) {
                int pos = nq + __popc(m & ((1u << lane) - 1u));
                sql[w][pos] = (int)(e & 0xFFFFFFFFu);
            }
            nq += __popc(m);
        }
        __syncwarp();
        unsigned long long best = ~0ull;
        const float* ccd = g_cc + (size_t)dep * K;
        for (int q = 0; q < nq; q++) {
            int cand = sql[w][q];
            const float4* cr = (const float4*)(cb + (size_t)cand * D);
            float4 c0 = cr[lane * 2], c1 = cr[lane * 2 + 1];
            float p = r0.x * c0.x + r0.y * c0.y + r0.z * c0.z + r0.w * c0.w
                    + r1.x * c1.x + r1.y * c1.y + r1.z * c1.z + r1.w * c1.w;
#pragma unroll
            for (int o = 16; o > 0; o >>= 1) p += __shfl_xor_sync(0xffffffffu, p, o);
            float dist = ccd[cand] - 2.f * p;
            unsigned long long key =
                ((unsigned long long)f2ord(dist) << 32) | (unsigned int)cand;
            if (key < best) best = key;
        }
        idx = (int)(best & 0xFFFFFFFFu);
    }

    // ---- update: each lane owns 8 contiguous elements; agg = x - res ----
    const size_t o4 = (size_t)row * (D / 4) + lane * 2;
    const float4* cbv = (const float4*)(cb + (size_t)idx * D);
    float4 q0 = cbv[lane * 2], q1 = cbv[lane * 2 + 1];
    float4 x0 = ((const float4*)x)[o4], x1 = ((const float4*)x)[o4 + 1];

    float4 n0, n1;
    n0.x = r0.x - q0.x; n0.y = r0.y - q0.y; n0.z = r0.z - q0.z; n0.w = r0.w - q0.w;
    n1.x = r1.x - q1.x; n1.y = r1.y - q1.y; n1.z = r1.z - q1.z; n1.w = r1.w - q1.w;

    // a = x - r_new  (aggregate), diff = x - a
    float4 a0, a1;
    a0.x = x0.x - n0.x; a0.y = x0.y - n0.y; a0.z = x0.z - n0.z; a0.w = x0.w - n0.w;
    a1.x = x1.x - n1.x; a1.y = x1.y - n1.y; a1.z = x1.z - n1.z; a1.w = x1.w - n1.w;

    if (dep < DEPTH - 1) {
        ((float4*)g_res)[o4] = n0;
        ((float4*)g_res)[o4 + 1] = n1;
        uint4 hh;
        hh.x = h2_as_u32(__float22half2_rn(make_float2(n0.x, n0.y)));
        hh.y = h2_as_u32(__float22half2_rn(make_float2(n0.z, n0.w)));
        hh.z = h2_as_u32(__float22half2_rn(make_float2(n1.x, n1.y)));
        hh.w = h2_as_u32(__float22half2_rn(make_float2(n1.z, n1.w)));
        *(uint4*)(g_res_h + (size_t)row * D + lane * 8) = hh;
    } else {
        float4 ov0, ov1;
        ov0.x = x0.x + (a0.x - x0.x); ov0.y = x0.y + (a0.y - x0.y);
        ov0.z = x0.z + (a0.z - x0.z); ov0.w = x0.w + (a0.w - x0.w);
        ov1.x = x1.x + (a1.x - x1.x); ov1.y = x1.y + (a1.y - x1.y);
        ov1.z = x1.z + (a1.z - x1.z); ov1.w = x1.w + (a1.w - x1.w);
        ((float4*)out)[o4] = ov0;
        ((float4*)out)[o4 + 1] = ov1;
    }

    float d0x = x0.x - a0.x, d0y = x0.y - a0.y, d0z = x0.z - a0.z, d0w = x0.w - a0.w;
    float d1x = x1.x - a1.x, d1y = x1.y - a1.y, d1z = x1.z - a1.z, d1w = x1.w - a1.w;
    float s2 = d0x * d0x + d0y * d0y + d0z * d0z + d0w * d0w
             + d1x * d1x + d1y * d1y + d1z * d1z + d1w * d1w;
#pragma unroll
    for (int o = 16; o > 0; o >>= 1) s2 += __shfl_down_sync(0xffffffffu, s2, o);
    if (lane == 0) {
        wloss[w] = s2;
        codes[(size_t)row * DEPTH + dep] = (float)idx;
    }
    __syncthreads();
    if (threadIdx.x == 0) {
        float t = 0.f;
#pragma unroll
        for (int i = 0; i < 8; i++) t += wloss[i];
        atomicAdd(loss, t * LOSS_SCALE);
    }
}

extern "C" void kernel_launch(void* const* d_in, const int* in_sizes, int n_in,
                              void* d_out, int out_size) {
    const float* x = (const float*)d_in[0];
    const float* cbs = (const float*)d_in[1];
    float* out = (float*)d_out;
    float* loss = out + (size_t)N_ROWS * D;
    float* codes = loss + 1;

    cudaFuncSetAttribute(k_gemm, cudaFuncAttributeMaxDynamicSharedMemorySize, SMEMT);

    k_init<<<(N_ROWS * D / 4) / 256, 256>>>(x, loss);
    k_cb<<<DEPTH * K, 64>>>(cbs);

    for (int d = 0; d < DEPTH; d++) {
        const float* cb = cbs + (size_t)d * CB_STRIDE;
        dim3 grid(N_ROWS / BM, K / 256);
        k_gemm<<<grid, 256, SMEMT>>>(d);
        k_finish<<<N_ROWS / 8, 256>>>(x, cb, out, codes, loss, d);
    }
}